// round 16
// baseline (speedup 1.0000x reference)
#include <cuda_runtime.h>
#include <cstdint>

// T=8192, B=512, H=16, IN=1, OUT=5; output = FC(GRU hidden of batch index 511).
#define T_LEN 8192
#define BATCH 512
#define HID   16
#define NOUT  5

// Transposed history, one private row per LANE; rows 16..31 garbage. fc reads 0..15.
__device__ float g_hist[32 * T_LEN];

__device__ __forceinline__ float tanhap(float x) {
    float y; asm("tanh.approx.f32 %0, %1;" : "=f"(y) : "f"(x)); return y;
}
__device__ __forceinline__ unsigned long long pk2(float lo, float hi) {
    unsigned long long r; asm("mov.b64 %0, {%1, %2};" : "=l"(r) : "f"(lo), "f"(hi)); return r;
}
__device__ __forceinline__ void upk2(float& lo, float& hi, unsigned long long v) {
    asm("mov.b64 {%0, %1}, %2;" : "=f"(lo), "=f"(hi) : "l"(v));
}
__device__ __forceinline__ unsigned long long fma2(unsigned long long a, unsigned long long b,
                                                   unsigned long long c) {
    unsigned long long d;
    asm("fma.rn.f32x2 %0, %1, %2, %3;" : "=l"(d) : "l"(a), "l"(b), "l"(c));
    return d;
}
__device__ __forceinline__ unsigned long long add2(unsigned long long a, unsigned long long b) {
    unsigned long long d;
    asm("add.rn.f32x2 %0, %1, %2;" : "=l"(d) : "l"(a), "l"(b));
    return d;
}
__device__ __forceinline__ uint32_t smem_u32(const void* p) {
    uint32_t a;
    asm("{ .reg .u64 t; cvta.to.shared.u64 t, %1; cvt.u32.u64 %0, t; }" : "=r"(a) : "l"(p));
    return a;
}

__global__ void __launch_bounds__(32, 1)
gru_seq_kernel(const float* __restrict__ x,
               const float* __restrict__ w_ih,
               const float* __restrict__ w_hh,
               const float* __restrict__ b_ih,
               const float* __restrict__ b_hh)
{
    // Slots 0..15: hidden state (low lanes). 16..31: dummy sink (32 distinct STS).
    __shared__ __align__(16) float hbuf[32];
    const unsigned FULL = 0xffffffffu;
    const int lane = threadIdx.x;
    const int j    = lane & 15;
    const bool low = lane < 16;

    // dotA row = r-row j (low) / z-row j (high); sigmoid via 0.5+0.5*tanh(v/2),
    // gate rows pre-halved. n-dot SPLIT across the lane pair: each half computes
    // 8 of 16 terms; shfl_xor(16) + add combines to full D = 0.5*(w_n.h + b_n).
    // narg = xgn + D + t_r*D. Tail: hn = P + tz*Q, P/Q from hh = 0.5*h_own.
    //
    // Per-half LDS permutation: low lanes load h-pairs 0..3 first, high lanes
    // pairs 4..7 first — so g0..g3 are ALWAYS the lane's own n-half operands.
    // Weight registers are permuted to match at setup (zero in-loop selects).
    const int rowA = low ? j : (HID + j);

    unsigned long long wA[8], wnh[4];
    #pragma unroll
    for (int k = 0; k < 8; ++k) {
        const float* ra = &w_hh[rowA * HID];
        const int p = low ? k : (k ^ 4);            // pair index held in g_k
        wA[k] = pk2(0.5f * ra[2 * p], 0.5f * ra[2 * p + 1]);
    }
    #pragma unroll
    for (int k = 0; k < 4; ++k) {
        const float* rn = &w_hh[(2 * HID + j) * HID];
        const int p = low ? k : (k + 4);            // own n-half pair
        wnh[k] = pk2(0.5f * rn[2 * p], 0.5f * rn[2 * p + 1]);
    }
    const float wihA2  = 0.5f * w_ih[rowA];
    const float biasA2 = 0.5f * (b_ih[rowA] + b_hh[rowA]);
    const float wih_n  = w_ih[2 * HID + j];
    const float bih_n  = b_ih[2 * HID + j];
    // n-bias seeded on the LOW half only (full D assembled after the exchange)
    const unsigned long long bnseed = pk2(low ? 0.5f * b_hh[2 * HID + j] : 0.0f, 0.0f);
    const unsigned long long Z64 = 0ull;

    hbuf[lane] = 0.0f;
    __syncwarp();
    float hh = 0.0f;   // 0.5 * h_own

    const uint32_t sbase = smem_u32(&hbuf[0]);
    const uint32_t waddr = sbase + (uint32_t)(lane * 4);
    // per-half permuted load addresses (banks disjoint across halves)
    const uint32_t aOwn = sbase + (low ? 0u : 32u);     // own n-half pairs
    const uint32_t aOth = sbase + (low ? 32u : 0u);     // other pairs

    float4* histp = (float4*)&g_hist[lane * T_LEN];
    float4 hacc;

    const int xoff = BATCH - 1;
    float xv      = x[(0  + lane) * BATCH + xoff];
    float xv_next = x[(32 + lane) * BATCH + xoff];

    const int NCHUNK = T_LEN / 32;
    for (int c = 0; c < NCHUNK; ++c) {
        #pragma unroll
        for (int s = 0; s < 32; ++s) {
            // warp-synchronous roundtrip; own n-half pairs load first
            unsigned long long g0, g1, g2, g3, g4, g5, g6, g7;
            asm volatile("ld.shared.v2.u64 {%0, %1}, [%2];" : "=l"(g0), "=l"(g1) : "r"(aOwn));
            asm volatile("ld.shared.v2.u64 {%0, %1}, [%2];" : "=l"(g2), "=l"(g3) : "r"(aOwn + 16));
            asm volatile("ld.shared.v2.u64 {%0, %1}, [%2];" : "=l"(g4), "=l"(g5) : "r"(aOth));
            asm volatile("ld.shared.v2.u64 {%0, %1}, [%2];" : "=l"(g6), "=l"(g7) : "r"(aOth + 16));

            const float xt  = __shfl_sync(FULL, xv, s);
            const float xgA = fmaf(xt, wihA2, biasA2);
            const float xgn = fmaf(xt, wih_n,  bih_n);
            const unsigned long long seed_A = pk2(xgA, 0.0f);

            // n-half dot first (4 fma2) -> exchange partial early (off-path shfl)
            unsigned long long aN0, aN1;
            aN0 = fma2(wnh[0], g0, bnseed); aN1 = fma2(wnh[1], g1, Z64);
            aN0 = fma2(wnh[2], g2, aN0);    aN1 = fma2(wnh[3], g3, aN1);
            float lo_, hi_;
            upk2(lo_, hi_, add2(aN0, aN1)); const float Dpart = lo_ + hi_;
            const float Doth = __shfl_xor_sync(FULL, Dpart, 16);

            // dotA (8 fma2) over permuted pairs
            unsigned long long aA0, aA1;
            aA0 = fma2(wA[0], g0, seed_A); aA1 = fma2(wA[1], g1, Z64);
            aA0 = fma2(wA[2], g2, aA0);    aA1 = fma2(wA[3], g3, aA1);
            aA0 = fma2(wA[4], g4, aA0);    aA1 = fma2(wA[5], g5, aA1);
            aA0 = fma2(wA[6], g6, aA0);    aA1 = fma2(wA[7], g7, aA1);
            upk2(lo_, hi_, add2(aA0, aA1)); const float gA = lo_ + hi_;  // incl xgA

            const float t  = tanhap(gA);                 // r (low) | z (high)
            const float tz = __shfl_xor_sync(FULL, t, 16);

            const float D    = Dpart + Doth;             // full 0.5*(w_n.h+b_n)
            const float xnD  = xgn + D;
            const float narg = fmaf(t, D, xnD);          // t == t_r on low
            const float n    = tanhap(narg);

            const float P  = fmaf( 0.5f, n, hh);
            const float Q  = fmaf(-0.5f, n, hh);
            const float hn = fmaf(tz, Q, P);             // valid on low lanes

            asm volatile("st.shared.f32 [%0], %1;" :: "r"(waddr), "f"(hn));
            hh = 0.5f * hn;

            if ((s & 3) == 0) hacc.x = hn;
            else if ((s & 3) == 1) hacc.y = hn;
            else if ((s & 3) == 2) hacc.z = hn;
            else { hacc.w = hn; *histp = hacc; ++histp; }
        }
        xv = xv_next;
        const int nc = (c + 2 < NCHUNK) ? (c + 2) : (NCHUNK - 1);
        xv_next = x[(nc * 32 + lane) * BATCH + xoff];
    }
}

// out[t][o] = h_t . fc_w[o] + fc_b[o]   (history rows 0..15 = hidden units)
__global__ void fc_kernel(const float* __restrict__ fc_w,
                          const float* __restrict__ fc_b,
                          float* __restrict__ out)
{
    const int i = blockIdx.x * blockDim.x + threadIdx.x;
    if (i >= T_LEN * NOUT) return;
    const int t = i / NOUT;
    const int o = i - t * NOUT;
    float acc = fc_b[o];
    #pragma unroll
    for (int k = 0; k < HID; ++k)
        acc = fmaf(g_hist[k * T_LEN + t], fc_w[o * HID + k], acc);
    out[i] = acc;
}

extern "C" void kernel_launch(void* const* d_in, const int* in_sizes, int n_in,
                              void* d_out, int out_size)
{
    const float* x    = (const float*)d_in[0];
    const float* w_ih = (const float*)d_in[1];
    const float* w_hh = (const float*)d_in[2];
    const float* b_ih = (const float*)d_in[3];
    const float* b_hh = (const float*)d_in[4];
    const float* fc_w = (const float*)d_in[5];
    const float* fc_b = (const float*)d_in[6];
    float* out = (float*)d_out;

    gru_seq_kernel<<<1, 32>>>(x, w_ih, w_hh, b_ih, b_hh);

    const int n = T_LEN * NOUT;
    fc_kernel<<<(n + 255) / 256, 256>>>(fc_w, fc_b, out);
}

// round 17
// speedup vs baseline: 1.0349x; 1.0349x over previous
#include <cuda_runtime.h>
#include <cstdint>

// T=8192, B=512, H=16, IN=1, OUT=5; output = FC(GRU hidden of batch index 511).
#define T_LEN 8192
#define BATCH 512
#define HID   16
#define NOUT  5

// Transposed history, one private row per LANE; rows 16..31 garbage. fc reads 0..15.
__device__ float g_hist[32 * T_LEN];

__device__ __forceinline__ float tanhap(float x) {
    float y; asm("tanh.approx.f32 %0, %1;" : "=f"(y) : "f"(x)); return y;
}
__device__ __forceinline__ unsigned long long pk2(float lo, float hi) {
    unsigned long long r; asm("mov.b64 %0, {%1, %2};" : "=l"(r) : "f"(lo), "f"(hi)); return r;
}
__device__ __forceinline__ void upk2(float& lo, float& hi, unsigned long long v) {
    asm("mov.b64 {%0, %1}, %2;" : "=f"(lo), "=f"(hi) : "l"(v));
}
__device__ __forceinline__ unsigned long long fma2(unsigned long long a, unsigned long long b,
                                                   unsigned long long c) {
    unsigned long long d;
    asm("fma.rn.f32x2 %0, %1, %2, %3;" : "=l"(d) : "l"(a), "l"(b), "l"(c));
    return d;
}
__device__ __forceinline__ unsigned long long add2(unsigned long long a, unsigned long long b) {
    unsigned long long d;
    asm("add.rn.f32x2 %0, %1, %2;" : "=l"(d) : "l"(a), "l"(b));
    return d;
}
__device__ __forceinline__ uint32_t smem_u32(const void* p) {
    uint32_t a;
    asm("{ .reg .u64 t; cvta.to.shared.u64 t, %1; cvt.u32.u64 %0, t; }" : "=r"(a) : "l"(p));
    return a;
}

__global__ void __launch_bounds__(32, 1)
gru_seq_kernel(const float* __restrict__ x,
               const float* __restrict__ w_ih,
               const float* __restrict__ w_hh,
               const float* __restrict__ b_ih,
               const float* __restrict__ b_hh)
{
    // Slots 0..15: hidden state (low lanes). 16..31: dummy sink (32 distinct STS).
    __shared__ __align__(16) float hbuf[32];
    const unsigned FULL = 0xffffffffu;
    const int lane = threadIdx.x;
    const int j    = lane & 15;

    // dotA row = r-row j (lanes<16) / z-row j (lanes>=16); sigmoid via
    // 0.5+0.5*tanh(v/2), gate rows pre-halved. n-dot on ALL lanes.
    // narg = xgn + D + t_r*D with D = 0.5*(w_n.h + b_n).
    // Tail: hn = P + tz*Q with hh = 0.5*h_own, P = hh + 0.5n, Q = hh - 0.5n.
    const int rowA = (lane < 16) ? j : (HID + j);

    unsigned long long wA[8], wn[8];
    #pragma unroll
    for (int k = 0; k < 8; ++k) {
        const float* ra = &w_hh[rowA * HID];
        const float* rn = &w_hh[(2 * HID + j) * HID];
        wA[k] = pk2(0.5f * ra[2 * k], 0.5f * ra[2 * k + 1]);
        wn[k] = pk2(0.5f * rn[2 * k], 0.5f * rn[2 * k + 1]);
    }
    const float wihA2  = 0.5f * w_ih[rowA];
    const float biasA2 = 0.5f * (b_ih[rowA] + b_hh[rowA]);
    const float wih_n  = w_ih[2 * HID + j];
    const float bih_n  = b_ih[2 * HID + j];
    const unsigned long long bn2pk = pk2(0.5f * b_hh[2 * HID + j], 0.0f);
    const unsigned long long Z64 = 0ull;

    hbuf[lane] = 0.0f;
    __syncwarp();
    float hh = 0.0f;   // 0.5 * h_own

    const uint32_t sbase = smem_u32(&hbuf[0]);
    const uint32_t waddr = sbase + (uint32_t)(lane * 4);

    float4* histp = (float4*)&g_hist[lane * T_LEN];
    float4 hacc;

    const int xoff = BATCH - 1;
    float xv      = x[(0  + lane) * BATCH + xoff];
    float xv_next = x[(32 + lane) * BATCH + xoff];

    // Software-rotated h registers: loaded at the END of the previous step,
    // immediately after its STS (prologue issues the first loads here).
    unsigned long long h0, h1, h2, h3, h4, h5, h6, h7;
    asm volatile("ld.shared.v2.u64 {%0, %1}, [%2];" : "=l"(h0), "=l"(h1) : "r"(sbase));
    asm volatile("ld.shared.v2.u64 {%0, %1}, [%2];" : "=l"(h2), "=l"(h3) : "r"(sbase + 16));
    asm volatile("ld.shared.v2.u64 {%0, %1}, [%2];" : "=l"(h4), "=l"(h5) : "r"(sbase + 32));
    asm volatile("ld.shared.v2.u64 {%0, %1}, [%2];" : "=l"(h6), "=l"(h7) : "r"(sbase + 48));

    const int NCHUNK = T_LEN / 32;
    for (int c = 0; c < NCHUNK; ++c) {
        #pragma unroll
        for (int s = 0; s < 32; ++s) {
            // x-gate terms (independent of h)
            const float xt  = __shfl_sync(FULL, xv, s);
            const float xgA = fmaf(xt, wihA2, biasA2);
            const float xgn = fmaf(xt, wih_n,  bih_n);
            const unsigned long long seed_A = pk2(xgA, 0.0f);

            // two 16-dots: dotA (r|z by half), dotN. 16 fma2 total.
            unsigned long long aA0, aA1, aN0, aN1;
            aA0 = fma2(wA[0], h0, seed_A); aA1 = fma2(wA[1], h1, Z64);
            aN0 = fma2(wn[0], h0, bn2pk);  aN1 = fma2(wn[1], h1, Z64);
            aA0 = fma2(wA[2], h2, aA0);    aA1 = fma2(wA[3], h3, aA1);
            aN0 = fma2(wn[2], h2, aN0);    aN1 = fma2(wn[3], h3, aN1);
            aA0 = fma2(wA[4], h4, aA0);    aA1 = fma2(wA[5], h5, aA1);
            aN0 = fma2(wn[4], h4, aN0);    aN1 = fma2(wn[5], h5, aN1);
            aA0 = fma2(wA[6], h6, aA0);    aA1 = fma2(wA[7], h7, aA1);
            aN0 = fma2(wn[6], h6, aN0);    aN1 = fma2(wn[7], h7, aN1);

            float lo, hi;
            upk2(lo, hi, add2(aA0, aA1)); const float gA = lo + hi;   // incl xgA
            upk2(lo, hi, add2(aN0, aN1)); const float D  = lo + hi;   // 0.5*(w_n.h+b_n)

            // one MUFU covers both gates; tz shfl issued right after t
            const float t  = tanhap(gA);
            const float tz = __shfl_xor_sync(FULL, t, 16);   // low lanes: t_z

            const float xnD  = xgn + D;
            const float narg = fmaf(t, D, xnD);              // t == t_r on low
            const float n    = tanhap(narg);

            const float P  = fmaf( 0.5f, n, hh);
            const float Q  = fmaf(-0.5f, n, hh);
            const float hn = fmaf(tz, Q, P);                 // valid on low lanes

            // STS then IMMEDIATELY the next step's loads (volatile order pins
            // the SASS schedule); bookkeeping issues under the LDS flight time.
            asm volatile("st.shared.f32 [%0], %1;" :: "r"(waddr), "f"(hn));
            asm volatile("ld.shared.v2.u64 {%0, %1}, [%2];" : "=l"(h0), "=l"(h1) : "r"(sbase));
            asm volatile("ld.shared.v2.u64 {%0, %1}, [%2];" : "=l"(h2), "=l"(h3) : "r"(sbase + 16));
            asm volatile("ld.shared.v2.u64 {%0, %1}, [%2];" : "=l"(h4), "=l"(h5) : "r"(sbase + 32));
            asm volatile("ld.shared.v2.u64 {%0, %1}, [%2];" : "=l"(h6), "=l"(h7) : "r"(sbase + 48));

            hh = 0.5f * hn;
            if ((s & 3) == 0) hacc.x = hn;
            else if ((s & 3) == 1) hacc.y = hn;
            else if ((s & 3) == 2) hacc.z = hn;
            else { hacc.w = hn; *histp = hacc; ++histp; }
        }
        xv = xv_next;
        const int nc = (c + 2 < NCHUNK) ? (c + 2) : (NCHUNK - 1);   // branch-free
        xv_next = x[(nc * 32 + lane) * BATCH + xoff];
    }
}

// out[t][o] = h_t . fc_w[o] + fc_b[o]   (history rows 0..15 = hidden units)
__global__ void fc_kernel(const float* __restrict__ fc_w,
                          const float* __restrict__ fc_b,
                          float* __restrict__ out)
{
    const int i = blockIdx.x * blockDim.x + threadIdx.x;
    if (i >= T_LEN * NOUT) return;
    const int t = i / NOUT;
    const int o = i - t * NOUT;
    float acc = fc_b[o];
    #pragma unroll
    for (int k = 0; k < HID; ++k)
        acc = fmaf(g_hist[k * T_LEN + t], fc_w[o * HID + k], acc);
    out[i] = acc;
}

extern "C" void kernel_launch(void* const* d_in, const int* in_sizes, int n_in,
                              void* d_out, int out_size)
{
    const float* x    = (const float*)d_in[0];
    const float* w_ih = (const float*)d_in[1];
    const float* w_hh = (const float*)d_in[2];
    const float* b_ih = (const float*)d_in[3];
    const float* b_hh = (const float*)d_in[4];
    const float* fc_w = (const float*)d_in[5];
    const float* fc_b = (const float*)d_in[6];
    float* out = (float*)d_out;

    gru_seq_kernel<<<1, 32>>>(x, w_ih, w_hh, b_ih, b_hh);

    const int n = T_LEN * NOUT;
    fc_kernel<<<(n + 255) / 256, 256>>>(fc_w, fc_b, out);
}